// round 4
// baseline (speedup 1.0000x reference)
#include <cuda_runtime.h>
#include <cuda_bf16.h>

// VectorQuantizer: z (65536 x 64 fp32), codebook (1024 x 64 fp32).
// For each row: argmin_v |z|^2 + |c_v|^2 - 2 z.c_v ; outputs:
//   [0, 4194304)            z_quantized = codebook[token]  (fp32)
//   [4194304, 4259840)      tokens (as fp32)
//   [4259840, 4325376)      codebook copy (fp32)

#define NROWS 65536
#define DDIM  64
#define VOCAB 1024
#define TILE_V 128
#define THREADS 128
#define RPT 2   // rows per thread

__device__ float d_c2[VOCAB];  // codebook squared norms

// ---- packed f32x2 helpers (sm_100+ PTX) ----
__device__ __forceinline__ unsigned long long ffma2(unsigned long long a,
                                                    unsigned long long b,
                                                    unsigned long long c) {
    unsigned long long d;
    asm("fma.rn.f32x2 %0, %1, %2, %3;" : "=l"(d) : "l"(a), "l"(b), "l"(c));
    return d;
}
__device__ __forceinline__ unsigned long long fadd2(unsigned long long a,
                                                    unsigned long long b) {
    unsigned long long d;
    asm("add.rn.f32x2 %0, %1, %2;" : "=l"(d) : "l"(a), "l"(b));
    return d;
}
__device__ __forceinline__ float2 unpack2(unsigned long long x) {
    unsigned lo, hi;
    asm("mov.b64 {%0, %1}, %2;" : "=r"(lo), "=r"(hi) : "l"(x));
    float2 r;
    r.x = __uint_as_float(lo);
    r.y = __uint_as_float(hi);
    return r;
}

__global__ void vq_prep_kernel(const float* __restrict__ cb) {
    int v = blockIdx.x * blockDim.x + threadIdx.x;
    if (v < VOCAB) {
        const float4* p = reinterpret_cast<const float4*>(cb + (size_t)v * DDIM);
        float s = 0.f;
#pragma unroll
        for (int i = 0; i < 16; i++) {
            float4 q = p[i];
            s += q.x * q.x + q.y * q.y + q.z * q.z + q.w * q.w;
        }
        d_c2[v] = s;
    }
}

__global__ void __launch_bounds__(THREADS, 2)
vq_main_kernel(const float* __restrict__ z, const float* __restrict__ cb,
               float* __restrict__ out_q, float* __restrict__ out_tok) {
    __shared__ float4 s_cb[TILE_V * 16];  // 128 codes x 64 floats = 32KB
    __shared__ float  s_c2[TILE_V];

    const int tid = threadIdx.x;
    const int row0 = (blockIdx.x * THREADS + tid) * RPT;

    // Load 2 z rows into registers, pre-packed as f32x2 pairs along D.
    unsigned long long a0[32], a1[32];
    {
        const ulonglong2* z0 =
            reinterpret_cast<const ulonglong2*>(z + (size_t)row0 * DDIM);
        const ulonglong2* z1 =
            reinterpret_cast<const ulonglong2*>(z + (size_t)(row0 + 1) * DDIM);
#pragma unroll
        for (int i = 0; i < 16; i++) {
            ulonglong2 t0 = z0[i], t1 = z1[i];
            a0[2 * i] = t0.x; a0[2 * i + 1] = t0.y;
            a1[2 * i] = t1.x; a1[2 * i + 1] = t1.y;
        }
    }

    // |z|^2 per row
    float d1_0 = 0.f, d1_1 = 0.f;
#pragma unroll
    for (int i = 0; i < 32; i++) {
        float2 p = unpack2(a0[i]);
        d1_0 += p.x * p.x + p.y * p.y;
        float2 q = unpack2(a1[i]);
        d1_1 += q.x * q.x + q.y * q.y;
    }

    float best0 = 3.402823466e+38f, best1 = 3.402823466e+38f;
    int bi0 = 0, bi1 = 0;

    for (int t = 0; t < VOCAB / TILE_V; t++) {
        // Stage codebook tile + norms into smem
        const float4* g =
            reinterpret_cast<const float4*>(cb + (size_t)t * TILE_V * DDIM);
        for (int i = tid; i < TILE_V * 16; i += THREADS) s_cb[i] = g[i];
        s_c2[tid] = d_c2[t * TILE_V + tid];  // THREADS == TILE_V
        __syncthreads();

#pragma unroll 1
        for (int v = 0; v < TILE_V; v++) {
            const ulonglong2* cp =
                reinterpret_cast<const ulonglong2*>(s_cb + v * 16);
            unsigned long long acc00 = 0ull, acc01 = 0ull;
            unsigned long long acc10 = 0ull, acc11 = 0ull;
#pragma unroll
            for (int j = 0; j < 16; j++) {
                ulonglong2 b = cp[j];  // LDS.128 broadcast: c[4j..4j+3]
                acc00 = ffma2(a0[2 * j],     b.x, acc00);
                acc01 = ffma2(a0[2 * j + 1], b.y, acc01);
                acc10 = ffma2(a1[2 * j],     b.x, acc10);
                acc11 = ffma2(a1[2 * j + 1], b.y, acc11);
            }
            float2 s0 = unpack2(fadd2(acc00, acc01));
            float2 s1 = unpack2(fadd2(acc10, acc11));
            float dot0 = s0.x + s0.y;
            float dot1 = s1.x + s1.y;
            float c2 = s_c2[v];
            // (d1 + d2) - 2*dot, non-fused to mirror reference expression
            float dist0 = __fsub_rn(__fadd_rn(d1_0, c2), __fmul_rn(2.0f, dot0));
            float dist1 = __fsub_rn(__fadd_rn(d1_1, c2), __fmul_rn(2.0f, dot1));
            int gv = t * TILE_V + v;
            if (dist0 < best0) { best0 = dist0; bi0 = gv; }
            if (dist1 < best1) { best1 = dist1; bi1 = gv; }
        }
        __syncthreads();
    }

    // Epilogue: tokens (as float) + gather quantized vectors
    out_tok[row0]     = (float)bi0;
    out_tok[row0 + 1] = (float)bi1;
    const float4* c0 = reinterpret_cast<const float4*>(cb + (size_t)bi0 * DDIM);
    const float4* c1 = reinterpret_cast<const float4*>(cb + (size_t)bi1 * DDIM);
    float4* o0 = reinterpret_cast<float4*>(out_q + (size_t)row0 * DDIM);
    float4* o1 = reinterpret_cast<float4*>(out_q + (size_t)(row0 + 1) * DDIM);
#pragma unroll
    for (int i = 0; i < 16; i++) { o0[i] = c0[i]; o1[i] = c1[i]; }
}

extern "C" void kernel_launch(void* const* d_in, const int* in_sizes, int n_in,
                              void* d_out, int out_size) {
    const float* z  = (const float*)d_in[0];
    const float* cb = (const float*)d_in[1];
    float* out = (float*)d_out;

    float* out_q   = out;                       // 65536*64
    float* out_tok = out + (size_t)NROWS * DDIM;     // 65536
    float* out_cb  = out_tok + NROWS;                // 1024*64

    vq_prep_kernel<<<(VOCAB + 255) / 256, 256>>>(cb);
    vq_main_kernel<<<NROWS / (THREADS * RPT), THREADS>>>(z, cb, out_q, out_tok);
    cudaMemcpyAsync(out_cb, cb, (size_t)VOCAB * DDIM * sizeof(float),
                    cudaMemcpyDeviceToDevice);
}

// round 12
// speedup vs baseline: 1.1736x; 1.1736x over previous
#include <cuda_runtime.h>
#include <cuda_bf16.h>
#include <cstdint>

// VectorQuantizer via mma.sync (HMMA) bf16 3-split GEMM (compute_103-safe).
// z: 65536 x 64 fp32, codebook: 1024 x 64 fp32.
// argmin_v (|c_v|^2 - 2 z.c_v)   [ |z|^2 row-constant, dropped ]
// out: [z_q 65536*64 | tokens 65536 (float) | codebook 1024*64]

#define NROWS   65536
#define DDIM    64
#define VOCAB   1024
#define THREADS 256          // 8 warps; CTA covers 128 rows (16 rows/warp)
#define M_CTA   128
#define N_CHUNK 128          // codes staged per smem chunk
#define NCHUNKS (VOCAB / N_CHUNK)

// smem: B chunk 3 splits x 128 codes x 144B (pad 64 bf16 -> 72), then c2[1024]
#define ROWPITCH 144
#define SMEM_B   0
#define SMEM_BSZ (3 * N_CHUNK * ROWPITCH)      // 55296
#define SMEM_C2  SMEM_BSZ                      // 4096 bytes
#define SMEM_TOTAL (SMEM_BSZ + VOCAB * 4)      // 59392

__device__ __nv_bfloat16 d_cb_split[3][VOCAB][DDIM];
__device__ float d_c2[VOCAB];

__device__ __forceinline__ void split3(float x, unsigned short h[3]) {
    __nv_bfloat16 b1 = __float2bfloat16(x);
    float r1 = x - __bfloat162float(b1);
    __nv_bfloat16 b2 = __float2bfloat16(r1);
    float r2 = r1 - __bfloat162float(b2);
    __nv_bfloat16 b3 = __float2bfloat16(r2);
    h[0] = __bfloat16_as_ushort(b1);
    h[1] = __bfloat16_as_ushort(b2);
    h[2] = __bfloat16_as_ushort(b3);
}

// m16n8k16 row.col f32.bf16.bf16.f32 — PTX ISA baseline (sm_80+)
#define MMA16816(C0, C1, C2, C3, A0, A1, A2, A3, B0, B1)                      \
    asm volatile(                                                             \
        "mma.sync.aligned.m16n8k16.row.col.f32.bf16.bf16.f32 "                \
        "{%0,%1,%2,%3}, {%4,%5,%6,%7}, {%8,%9}, {%0,%1,%2,%3};"               \
        : "+f"(C0), "+f"(C1), "+f"(C2), "+f"(C3)                              \
        : "r"(A0), "r"(A1), "r"(A2), "r"(A3), "r"(B0), "r"(B1))

// ---------------- prep: codebook splits + squared norms ----------------------
__global__ void vq_prep_kernel(const float* __restrict__ cb) {
    int v = blockIdx.x * blockDim.x + threadIdx.x;
    if (v >= VOCAB) return;
    const float* row = cb + (size_t)v * DDIM;
    float s = 0.f;
    for (int c = 0; c < DDIM; c++) {
        float x = row[c];
        s += x * x;
        unsigned short h[3];
        split3(x, h);
        d_cb_split[0][v][c] = __ushort_as_bfloat16(h[0]);
        d_cb_split[1][v][c] = __ushort_as_bfloat16(h[1]);
        d_cb_split[2][v][c] = __ushort_as_bfloat16(h[2]);
    }
    d_c2[v] = s;
}

// ---------------- main HMMA kernel -------------------------------------------
__global__ void __launch_bounds__(THREADS, 2)
vq_mma_kernel(const float* __restrict__ z, const float* __restrict__ cb,
              float* __restrict__ out_q, float* __restrict__ out_tok) {
    extern __shared__ char smem[];
    char* smemB = smem + SMEM_B;
    float* s_c2 = reinterpret_cast<float*>(smem + SMEM_C2);

    const int tid  = threadIdx.x;
    const int w    = tid >> 5;
    const int lane = tid & 31;
    const int qrow = lane >> 2;   // 0..7
    const int qcol = lane & 3;    // 0..3

    const int rowLo = blockIdx.x * M_CTA + w * 16 + qrow;
    const int rowHi = rowLo + 8;

    // stage c2 (whole vocab, 4KB)
    for (int i = tid; i < VOCAB; i += THREADS) s_c2[i] = d_c2[i];

    // Build A fragments: 3 splits x 4 ktiles x 4 regs, straight from gmem z.
    // m16n8k16 A layout: a0=(r=qrow,  k=2q..+1)  a1=(r=qrow+8, k=2q..+1)
    //                    a2=(r=qrow,  k=2q+8..)  a3=(r=qrow+8, k=2q+8..)
    unsigned A[3][4][4];
#pragma unroll
    for (int t = 0; t < 4; t++) {
        const int c = t * 16 + qcol * 2;
        float2 v00 = *reinterpret_cast<const float2*>(z + (size_t)rowLo * DDIM + c);
        float2 v10 = *reinterpret_cast<const float2*>(z + (size_t)rowHi * DDIM + c);
        float2 v01 = *reinterpret_cast<const float2*>(z + (size_t)rowLo * DDIM + c + 8);
        float2 v11 = *reinterpret_cast<const float2*>(z + (size_t)rowHi * DDIM + c + 8);
        unsigned short hx[3], hy[3];
        split3(v00.x, hx); split3(v00.y, hy);
#pragma unroll
        for (int s = 0; s < 3; s++) A[s][t][0] = (unsigned)hx[s] | ((unsigned)hy[s] << 16);
        split3(v10.x, hx); split3(v10.y, hy);
#pragma unroll
        for (int s = 0; s < 3; s++) A[s][t][1] = (unsigned)hx[s] | ((unsigned)hy[s] << 16);
        split3(v01.x, hx); split3(v01.y, hy);
#pragma unroll
        for (int s = 0; s < 3; s++) A[s][t][2] = (unsigned)hx[s] | ((unsigned)hy[s] << 16);
        split3(v11.x, hx); split3(v11.y, hy);
#pragma unroll
        for (int s = 0; s < 3; s++) A[s][t][3] = (unsigned)hx[s] | ((unsigned)hy[s] << 16);
    }

    float bLo = 3.402823466e+38f, bHi = 3.402823466e+38f;
    int   iLo = 0, iHi = 0;

    for (int chunk = 0; chunk < NCHUNKS; chunk++) {
        __syncthreads();  // WAR: previous chunk fully consumed
        // stage B chunk: 3 splits x 128 codes x 128B payload into 144B rows
        const int base = chunk * N_CHUNK;
        for (int i = tid; i < 3 * N_CHUNK * 8; i += THREADS) {
            int s = i >> 10, rem = i & 1023, code = rem >> 3, c16 = rem & 7;
            uint4 v = reinterpret_cast<const uint4*>(&d_cb_split[s][base + code][0])[c16];
            *reinterpret_cast<uint4*>(smemB + (s * N_CHUNK + code) * ROWPITCH + c16 * 16) = v;
        }
        __syncthreads();

#pragma unroll 1
        for (int n8 = 0; n8 < N_CHUNK / 8; n8++) {
            // B fragments: col-major k16xn8: b0 k=2q.., b1 k=2q+8..; n = qrow
            const int codeB = n8 * 8 + qrow;
            unsigned Bf[3][4][2];
#pragma unroll
            for (int s = 0; s < 3; s++) {
                const char* rowp = smemB + (s * N_CHUNK + codeB) * ROWPITCH + qcol * 4;
#pragma unroll
                for (int t = 0; t < 4; t++) {
                    Bf[s][t][0] = *reinterpret_cast<const unsigned*>(rowp + t * 32);
                    Bf[s][t][1] = *reinterpret_cast<const unsigned*>(rowp + t * 32 + 16);
                }
            }

            // two accumulator chains (12 HMMA each) for latency cover
            float Ca0 = 0.f, Ca1 = 0.f, Ca2 = 0.f, Ca3 = 0.f;
            float Cb0 = 0.f, Cb1 = 0.f, Cb2 = 0.f, Cb3 = 0.f;
#pragma unroll
            for (int t = 0; t < 4; t++) {
                MMA16816(Ca0, Ca1, Ca2, Ca3, A[0][t][0], A[0][t][1], A[0][t][2], A[0][t][3], Bf[0][t][0], Bf[0][t][1]);
                MMA16816(Cb0, Cb1, Cb2, Cb3, A[0][t][0], A[0][t][1], A[0][t][2], A[0][t][3], Bf[1][t][0], Bf[1][t][1]);
                MMA16816(Ca0, Ca1, Ca2, Ca3, A[1][t][0], A[1][t][1], A[1][t][2], A[1][t][3], Bf[0][t][0], Bf[0][t][1]);
                MMA16816(Cb0, Cb1, Cb2, Cb3, A[0][t][0], A[0][t][1], A[0][t][2], A[0][t][3], Bf[2][t][0], Bf[2][t][1]);
                MMA16816(Ca0, Ca1, Ca2, Ca3, A[2][t][0], A[2][t][1], A[2][t][2], A[2][t][3], Bf[0][t][0], Bf[0][t][1]);
                MMA16816(Cb0, Cb1, Cb2, Cb3, A[1][t][0], A[1][t][1], A[1][t][2], A[1][t][3], Bf[1][t][0], Bf[1][t][1]);
            }

            // C layout: c0=(r=qrow, n=2q) c1=(r=qrow, n=2q+1) c2/c3 rows +8
            const int nc0 = base + n8 * 8 + qcol * 2;
            const int nc1 = nc0 + 1;
            const float c20 = s_c2[nc0], c21 = s_c2[nc1];
            float d00 = c20 - 2.0f * (Ca0 + Cb0);
            float d01 = c21 - 2.0f * (Ca1 + Cb1);
            float d10 = c20 - 2.0f * (Ca2 + Cb2);
            float d11 = c21 - 2.0f * (Ca3 + Cb3);
            if (d00 < bLo) { bLo = d00; iLo = nc0; }
            if (d01 < bLo) { bLo = d01; iLo = nc1; }
            if (d10 < bHi) { bHi = d10; iHi = nc0; }
            if (d11 < bHi) { bHi = d11; iHi = nc1; }
        }
    }

    // quad reduction (lanes 4q..4q+3 hold same rows, disjoint code subsets)
#pragma unroll
    for (int off = 1; off <= 2; off <<= 1) {
        float dl = __shfl_xor_sync(0xFFFFFFFFu, bLo, off);
        int   il = __shfl_xor_sync(0xFFFFFFFFu, iLo, off);
        if (dl < bLo || (dl == bLo && il < iLo)) { bLo = dl; iLo = il; }
        float dh = __shfl_xor_sync(0xFFFFFFFFu, bHi, off);
        int   ih = __shfl_xor_sync(0xFFFFFFFFu, iHi, off);
        if (dh < bHi || (dh == bHi && ih < iHi)) { bHi = dh; iHi = ih; }
    }

    if (qcol == 0) {
        out_tok[rowLo] = (float)iLo;
        out_tok[rowHi] = (float)iHi;
    }
    // quad-cooperative gather of the two winning codebook rows
    {
        const float4* sLo = reinterpret_cast<const float4*>(cb + (size_t)iLo * DDIM);
        const float4* sHi = reinterpret_cast<const float4*>(cb + (size_t)iHi * DDIM);
        float4* dLo = reinterpret_cast<float4*>(out_q + (size_t)rowLo * DDIM);
        float4* dHi = reinterpret_cast<float4*>(out_q + (size_t)rowHi * DDIM);
#pragma unroll
        for (int j = 0; j < 4; j++) {
            dLo[qcol + 4 * j] = sLo[qcol + 4 * j];
            dHi[qcol + 4 * j] = sHi[qcol + 4 * j];
        }
    }
}

extern "C" void kernel_launch(void* const* d_in, const int* in_sizes, int n_in,
                              void* d_out, int out_size) {
    const float* z  = (const float*)d_in[0];
    const float* cb = (const float*)d_in[1];
    float* out = (float*)d_out;

    float* out_q   = out;
    float* out_tok = out + (size_t)NROWS * DDIM;
    float* out_cb  = out_tok + NROWS;

    cudaFuncSetAttribute(vq_mma_kernel,
                         cudaFuncAttributeMaxDynamicSharedMemorySize, SMEM_TOTAL);

    vq_prep_kernel<<<(VOCAB + 255) / 256, 256>>>(cb);
    vq_mma_kernel<<<NROWS / M_CTA, THREADS, SMEM_TOTAL>>>(z, cb, out_q, out_tok);
    cudaMemcpyAsync(out_cb, cb, (size_t)VOCAB * DDIM * sizeof(float),
                    cudaMemcpyDeviceToDevice);
}

// round 13
// speedup vs baseline: 1.6896x; 1.4397x over previous
#include <cuda_runtime.h>
#include <cuda_bf16.h>
#include <cstdint>

// VectorQuantizer via mma.sync (HMMA) bf16 3-split GEMM + cp.async pipeline.
// z: 65536 x 64 fp32, codebook: 1024 x 64 fp32.
// argmin_v (|c_v|^2 - 2 z.c_v)   [ |z|^2 row-constant, dropped ]
// out: [z_q 65536*64 | tokens 65536 (float) | codebook 1024*64]

#define NROWS   65536
#define DDIM    64
#define VOCAB   1024
#define THREADS 256          // 8 warps; CTA covers 128 rows (16 rows/warp)
#define M_CTA   128
#define N_CHUNK 64           // codes per pipeline stage
#define NCHUNKS (VOCAB / N_CHUNK)   // 16

// smem: two B buffers (3 splits x 64 codes x 144B) + c2[1024]
#define ROWPITCH 144
#define BUFSZ    (3 * N_CHUNK * ROWPITCH)   // 27648
#define SMEM_C2  (2 * BUFSZ)                // 55296
#define SMEM_TOTAL (SMEM_C2 + VOCAB * 4)    // 59392

__device__ __nv_bfloat16 d_cb_split[3][VOCAB][DDIM];
__device__ float d_c2[VOCAB];

__device__ __forceinline__ void split3(float x, unsigned short h[3]) {
    __nv_bfloat16 b1 = __float2bfloat16(x);
    float r1 = x - __bfloat162float(b1);
    __nv_bfloat16 b2 = __float2bfloat16(r1);
    float r2 = r1 - __bfloat162float(b2);
    __nv_bfloat16 b3 = __float2bfloat16(r2);
    h[0] = __bfloat16_as_ushort(b1);
    h[1] = __bfloat16_as_ushort(b2);
    h[2] = __bfloat16_as_ushort(b3);
}

// m16n8k16 row.col f32.bf16.bf16.f32 — PTX ISA baseline (sm_80+)
#define MMA16816(C0, C1, C2, C3, A0, A1, A2, A3, B0, B1)                      \
    asm volatile(                                                             \
        "mma.sync.aligned.m16n8k16.row.col.f32.bf16.bf16.f32 "                \
        "{%0,%1,%2,%3}, {%4,%5,%6,%7}, {%8,%9}, {%0,%1,%2,%3};"               \
        : "+f"(C0), "+f"(C1), "+f"(C2), "+f"(C3)                              \
        : "r"(A0), "r"(A1), "r"(A2), "r"(A3), "r"(B0), "r"(B1))

#define CP_ASYNC16(dst_u32, src_ptr)                                          \
    asm volatile("cp.async.cg.shared.global [%0], [%1], 16;"                  \
                 :: "r"(dst_u32), "l"(src_ptr))
#define CP_COMMIT()  asm volatile("cp.async.commit_group;" ::: "memory")
#define CP_WAIT(n)   asm volatile("cp.async.wait_group %0;" :: "n"(n) : "memory")

__device__ __forceinline__ unsigned smem_u32(const void* p) {
    unsigned a;
    asm("{ .reg .u64 t; cvta.to.shared.u64 t, %1; cvt.u32.u64 %0, t; }" : "=r"(a) : "l"(p));
    return a;
}

// ---------------- prep: warp per code, lane = 2 columns ----------------------
__global__ void vq_prep_kernel(const float* __restrict__ cb) {
    const int gw   = (blockIdx.x * blockDim.x + threadIdx.x) >> 5;  // code id
    const int lane = threadIdx.x & 31;
    if (gw >= VOCAB) return;
    float2 v = *reinterpret_cast<const float2*>(cb + (size_t)gw * DDIM + lane * 2);
    unsigned short hx[3], hy[3];
    split3(v.x, hx); split3(v.y, hy);
#pragma unroll
    for (int s = 0; s < 3; s++) {
        ushort2 p; p.x = hx[s]; p.y = hy[s];
        *reinterpret_cast<ushort2*>(&d_cb_split[s][gw][lane * 2]) = p;
    }
    float ss = v.x * v.x + v.y * v.y;
#pragma unroll
    for (int off = 16; off >= 1; off >>= 1)
        ss += __shfl_xor_sync(0xFFFFFFFFu, ss, off);
    if (lane == 0) d_c2[gw] = ss;
}

// ---------------- main HMMA kernel with cp.async double buffer ---------------
__global__ void __launch_bounds__(THREADS, 2)
vq_mma_kernel(const float* __restrict__ z, const float* __restrict__ cb,
              float* __restrict__ out_q, float* __restrict__ out_tok) {
    extern __shared__ char smem[];
    float* s_c2 = reinterpret_cast<float*>(smem + SMEM_C2);
    const unsigned sbase = smem_u32(smem);

    const int tid  = threadIdx.x;
    const int w    = tid >> 5;
    const int lane = tid & 31;
    const int qrow = lane >> 2;   // 0..7
    const int qcol = lane & 3;    // 0..3

    const int rowLo = blockIdx.x * M_CTA + w * 16 + qrow;
    const int rowHi = rowLo + 8;

    // stage c2 (whole vocab, 4KB)
    for (int i = tid; i < VOCAB; i += THREADS) s_c2[i] = d_c2[i];

    // Build A fragments: 3 splits x 4 ktiles x 4 regs, straight from gmem z.
    unsigned A[3][4][4];
#pragma unroll
    for (int t = 0; t < 4; t++) {
        const int c = t * 16 + qcol * 2;
        float2 v00 = *reinterpret_cast<const float2*>(z + (size_t)rowLo * DDIM + c);
        float2 v10 = *reinterpret_cast<const float2*>(z + (size_t)rowHi * DDIM + c);
        float2 v01 = *reinterpret_cast<const float2*>(z + (size_t)rowLo * DDIM + c + 8);
        float2 v11 = *reinterpret_cast<const float2*>(z + (size_t)rowHi * DDIM + c + 8);
        unsigned short hx[3], hy[3];
        split3(v00.x, hx); split3(v00.y, hy);
#pragma unroll
        for (int s = 0; s < 3; s++) A[s][t][0] = (unsigned)hx[s] | ((unsigned)hy[s] << 16);
        split3(v10.x, hx); split3(v10.y, hy);
#pragma unroll
        for (int s = 0; s < 3; s++) A[s][t][1] = (unsigned)hx[s] | ((unsigned)hy[s] << 16);
        split3(v01.x, hx); split3(v01.y, hy);
#pragma unroll
        for (int s = 0; s < 3; s++) A[s][t][2] = (unsigned)hx[s] | ((unsigned)hy[s] << 16);
        split3(v11.x, hx); split3(v11.y, hy);
#pragma unroll
        for (int s = 0; s < 3; s++) A[s][t][3] = (unsigned)hx[s] | ((unsigned)hy[s] << 16);
    }

    float bLo = 3.402823466e+38f, bHi = 3.402823466e+38f;
    int   iLo = 0, iHi = 0;

    // stage chunk -> buffer via cp.async (6 x 16B per thread)
    auto stage = [&](int chunk, int buf) {
        const int base = chunk * N_CHUNK;
        const unsigned dst0 = sbase + buf * BUFSZ;
        for (int i = tid; i < 3 * N_CHUNK * 8; i += THREADS) {
            int s = i >> 9, rem = i & 511, code = rem >> 3, c16 = rem & 7;
            const void* src = &d_cb_split[s][base + code][c16 * 8];
            CP_ASYNC16(dst0 + (s * N_CHUNK + code) * ROWPITCH + c16 * 16, src);
        }
    };

    stage(0, 0);
    CP_COMMIT();

    for (int chunk = 0; chunk < NCHUNKS; chunk++) {
        __syncthreads();  // WAR: buffer (chunk+1)&1 fully consumed (chunk-1 compute)
        if (chunk + 1 < NCHUNKS) {
            stage(chunk + 1, (chunk + 1) & 1);
            CP_COMMIT();
            CP_WAIT(1);   // chunk's group done; chunk+1 may be in flight
        } else {
            CP_WAIT(0);
        }
        __syncthreads();

        const char* smemB = smem + (chunk & 1) * BUFSZ;
        const int base = chunk * N_CHUNK;

#pragma unroll 1
        for (int n8 = 0; n8 < N_CHUNK / 8; n8++) {
            const int codeB = n8 * 8 + qrow;
            unsigned Bf[3][4][2];
#pragma unroll
            for (int s = 0; s < 3; s++) {
                const char* rowp = smemB + (s * N_CHUNK + codeB) * ROWPITCH + qcol * 4;
#pragma unroll
                for (int t = 0; t < 4; t++) {
                    Bf[s][t][0] = *reinterpret_cast<const unsigned*>(rowp + t * 32);
                    Bf[s][t][1] = *reinterpret_cast<const unsigned*>(rowp + t * 32 + 16);
                }
            }

            float Ca0 = 0.f, Ca1 = 0.f, Ca2 = 0.f, Ca3 = 0.f;
            float Cb0 = 0.f, Cb1 = 0.f, Cb2 = 0.f, Cb3 = 0.f;
#pragma unroll
            for (int t = 0; t < 4; t++) {
                MMA16816(Ca0, Ca1, Ca2, Ca3, A[0][t][0], A[0][t][1], A[0][t][2], A[0][t][3], Bf[0][t][0], Bf[0][t][1]);
                MMA16816(Cb0, Cb1, Cb2, Cb3, A[0][t][0], A[0][t][1], A[0][t][2], A[0][t][3], Bf[1][t][0], Bf[1][t][1]);
                MMA16816(Ca0, Ca1, Ca2, Ca3, A[1][t][0], A[1][t][1], A[1][t][2], A[1][t][3], Bf[0][t][0], Bf[0][t][1]);
                MMA16816(Cb0, Cb1, Cb2, Cb3, A[0][t][0], A[0][t][1], A[0][t][2], A[0][t][3], Bf[2][t][0], Bf[2][t][1]);
                MMA16816(Ca0, Ca1, Ca2, Ca3, A[2][t][0], A[2][t][1], A[2][t][2], A[2][t][3], Bf[0][t][0], Bf[0][t][1]);
                MMA16816(Cb0, Cb1, Cb2, Cb3, A[1][t][0], A[1][t][1], A[1][t][2], A[1][t][3], Bf[1][t][0], Bf[1][t][1]);
            }

            const int nc0 = base + n8 * 8 + qcol * 2;
            const int nc1 = nc0 + 1;
            const float c20 = s_c2[nc0], c21 = s_c2[nc1];
            float d00 = c20 - 2.0f * (Ca0 + Cb0);
            float d01 = c21 - 2.0f * (Ca1 + Cb1);
            float d10 = c20 - 2.0f * (Ca2 + Cb2);
            float d11 = c21 - 2.0f * (Ca3 + Cb3);
            if (d00 < bLo) { bLo = d00; iLo = nc0; }
            if (d01 < bLo) { bLo = d01; iLo = nc1; }
            if (d10 < bHi) { bHi = d10; iHi = nc0; }
            if (d11 < bHi) { bHi = d11; iHi = nc1; }
        }
    }

    // quad reduction (lanes 4q..4q+3: same rows, disjoint code subsets)
#pragma unroll
    for (int off = 1; off <= 2; off <<= 1) {
        float dl = __shfl_xor_sync(0xFFFFFFFFu, bLo, off);
        int   il = __shfl_xor_sync(0xFFFFFFFFu, iLo, off);
        if (dl < bLo || (dl == bLo && il < iLo)) { bLo = dl; iLo = il; }
        float dh = __shfl_xor_sync(0xFFFFFFFFu, bHi, off);
        int   ih = __shfl_xor_sync(0xFFFFFFFFu, iHi, off);
        if (dh < bHi || (dh == bHi && ih < iHi)) { bHi = dh; iHi = ih; }
    }

    if (qcol == 0) {
        out_tok[rowLo] = (float)iLo;
        out_tok[rowHi] = (float)iHi;
    }
    {
        const float4* sLo = reinterpret_cast<const float4*>(cb + (size_t)iLo * DDIM);
        const float4* sHi = reinterpret_cast<const float4*>(cb + (size_t)iHi * DDIM);
        float4* dLo = reinterpret_cast<float4*>(out_q + (size_t)rowLo * DDIM);
        float4* dHi = reinterpret_cast<float4*>(out_q + (size_t)rowHi * DDIM);
#pragma unroll
        for (int j = 0; j < 4; j++) {
            dLo[qcol + 4 * j] = sLo[qcol + 4 * j];
            dHi[qcol + 4 * j] = sHi[qcol + 4 * j];
        }
    }
}

extern "C" void kernel_launch(void* const* d_in, const int* in_sizes, int n_in,
                              void* d_out, int out_size) {
    const float* z  = (const float*)d_in[0];
    const float* cb = (const float*)d_in[1];
    float* out = (float*)d_out;

    float* out_q   = out;
    float* out_tok = out + (size_t)NROWS * DDIM;
    float* out_cb  = out_tok + NROWS;

    cudaFuncSetAttribute(vq_mma_kernel,
                         cudaFuncAttributeMaxDynamicSharedMemorySize, SMEM_TOTAL);

    vq_prep_kernel<<<(VOCAB * 32) / THREADS, THREADS>>>(cb);
    vq_mma_kernel<<<NROWS / M_CTA, THREADS, SMEM_TOTAL>>>(z, cb, out_q, out_tok);
    cudaMemcpyAsync(out_cb, cb, (size_t)VOCAB * DDIM * sizeof(float),
                    cudaMemcpyDeviceToDevice);
}